// round 1
// baseline (speedup 1.0000x reference)
#include <cuda_runtime.h>

// pose3d_future loss:
//   total = 0.33 * mean_b[ sum_j ||proj(P)-E||^2 / 42 ]
//         + 0.50 * mean_b[ sum_bone (bl - |P_a - P_b|^2)^2 / 20 ]
// P: [B,3,21] f32, E: [B,2,21] f32, bl: [20], R: [3,3], C: [3,1], conn: [20,2] i64

#define NJ 21
#define NB 20

__device__ double g_acc[2];   // [0] = sum of per-sample proj sums, [1] = bone sums

__global__ void k_zero() {
    g_acc[0] = 0.0;
    g_acc[1] = 0.0;
}

__global__ __launch_bounds__(256) void k_loss(
    const float* __restrict__ pose,   // [B,3,21]
    const float* __restrict__ est,    // [B,2,21]
    const float* __restrict__ bl,     // [20]
    const float* __restrict__ R,      // [3,3]
    const float* __restrict__ C,      // [3,1]
    const long long* __restrict__ conn, // [20,2]
    int n)
{
    // M = K @ R^T, K = [[f,0,cx],[0,f,cy],[0,0,1]]
    // M[r][c] = sum_k K[r][k] * R[c][k]
    const float f = 525.0f, cx = 320.0f, cy = 240.0f;
    float M00 = f*R[0] + cx*R[2];
    float M01 = f*R[3] + cx*R[5];
    float M02 = f*R[6] + cx*R[8];
    float M10 = f*R[1] + cy*R[2];
    float M11 = f*R[4] + cy*R[5];
    float M12 = f*R[7] + cy*R[8];
    float M20 = R[2], M21 = R[5], M22 = R[8];
    float Cx = C[0], Cy = C[1], Cz = C[2];

    double accP = 0.0, accB = 0.0;

    for (int s = blockIdx.x * blockDim.x + threadIdx.x; s < n;
         s += gridDim.x * blockDim.x) {
        const float* __restrict__ P = pose + (size_t)s * (3 * NJ);
        const float* __restrict__ E = est  + (size_t)s * (2 * NJ);

        float psum = 0.0f;
        #pragma unroll
        for (int j = 0; j < NJ; j++) {
            float dx = P[j]        - Cx;
            float dy = P[NJ + j]   - Cy;
            float dz = P[2*NJ + j] - Cz;
            float px = M00*dx + M01*dy + M02*dz;
            float py = M10*dx + M11*dy + M12*dz;
            float pz = M20*dx + M21*dy + M22*dz;
            float inv = 1.0f / pz;
            float u = px * inv - E[j];
            float v = py * inv - E[NJ + j];
            psum += u*u + v*v;
        }

        float bsum = 0.0f;
        #pragma unroll
        for (int j = 0; j < NB; j++) {
            int a = (int)conn[2*j];
            int b = (int)conn[2*j + 1];
            float dx = P[a]        - P[b];
            float dy = P[NJ + a]   - P[NJ + b];
            float dz = P[2*NJ + a] - P[2*NJ + b];
            float sq = dx*dx + dy*dy + dz*dz;
            float t  = bl[j] - sq;
            bsum += t*t;
        }

        accP += (double)psum;
        accB += (double)bsum;
    }

    // warp reduce
    #pragma unroll
    for (int o = 16; o > 0; o >>= 1) {
        accP += __shfl_down_sync(0xffffffffu, accP, o);
        accB += __shfl_down_sync(0xffffffffu, accB, o);
    }

    __shared__ double sP[8], sB[8];
    int lane = threadIdx.x & 31;
    int wid  = threadIdx.x >> 5;
    if (lane == 0) { sP[wid] = accP; sB[wid] = accB; }
    __syncthreads();

    if (wid == 0) {
        int nw = blockDim.x >> 5;
        accP = (lane < nw) ? sP[lane] : 0.0;
        accB = (lane < nw) ? sB[lane] : 0.0;
        #pragma unroll
        for (int o = 4; o > 0; o >>= 1) {
            accP += __shfl_down_sync(0xffffffffu, accP, o);
            accB += __shfl_down_sync(0xffffffffu, accB, o);
        }
        if (lane == 0) {
            atomicAdd(&g_acc[0], accP);
            atomicAdd(&g_acc[1], accB);
        }
    }
}

__global__ void k_final(float* __restrict__ out, int n) {
    double invB = 1.0 / (double)n;
    double proj = g_acc[0] * invB / (2.0 * NJ);
    double bone = g_acc[1] * invB / (double)NB;
    out[0] = (float)(0.33 * proj + 0.5 * bone);
}

extern "C" void kernel_launch(void* const* d_in, const int* in_sizes, int n_in,
                              void* d_out, int out_size) {
    const float*     pose = (const float*)d_in[0];      // [B,3,21]
    const float*     est  = (const float*)d_in[1];      // [B,2,21]
    const float*     bl   = (const float*)d_in[2];      // [20]
    const float*     R    = (const float*)d_in[3];      // [3,3]
    const float*     C    = (const float*)d_in[4];      // [3,1]
    const long long* conn = (const long long*)d_in[5];  // [20,2]
    float* out = (float*)d_out;

    int n = in_sizes[0] / (3 * NJ);   // batch size

    k_zero<<<1, 1>>>();
    int threads = 256;
    int blocks  = (n + threads - 1) / threads;
    k_loss<<<blocks, threads>>>(pose, est, bl, R, C, conn, n);
    k_final<<<1, 1>>>(out, n);
}

// round 2
// speedup vs baseline: 2.5835x; 2.5835x over previous
#include <cuda_runtime.h>

// pose3d_future loss:
//   total = 0.33 * mean_b[ sum_j ||proj(P)-E||^2 / 42 ]
//         + 0.50 * mean_b[ sum_bone (bl - |P_a - P_b|^2)^2 / 20 ]
// P: [B,3,21] f32, E: [B,2,21] f32, bl: [20], R: [3,3], C: [3,1], conn: [20,2] i64

#define NJ 21
#define NB 20
#define TILE 128
#define THREADS 128
#define MAXBLK 1024

// dynamic smem layout: [TILE*63 pose][TILE*42 est][20 bl][40 conn(int)]
#define SM_POSE   0
#define SM_EST    (TILE * 63)
#define SM_BL     (SM_EST + TILE * 42)
#define SM_CONN   (SM_BL + NB)                 // stored as int
#define SM_FLOATS (SM_CONN + 2 * NB)
#define SMEM_BYTES (SM_FLOATS * 4)

__device__ double g_partP[MAXBLK];
__device__ double g_partB[MAXBLK];

__global__ __launch_bounds__(THREADS) void k_loss(
    const float* __restrict__ pose,     // [B,3,21]
    const float* __restrict__ est,      // [B,2,21]
    const float* __restrict__ bl,       // [20]
    const float* __restrict__ R,        // [3,3]
    const float* __restrict__ C,        // [3,1]
    const long long* __restrict__ conn, // [20,2]
    int n, int ntiles)
{
    extern __shared__ float sm[];
    float* smPose = sm + SM_POSE;
    float* smEst  = sm + SM_EST;
    float* smBl   = sm + SM_BL;
    int*   smConn = (int*)(sm + SM_CONN);

    int tid = threadIdx.x;

    // stage tiny tensors once
    if (tid < NB) {
        smBl[tid] = bl[tid];
        smConn[2 * tid]     = (int)conn[2 * tid];
        smConn[2 * tid + 1] = (int)conn[2 * tid + 1];
    }

    // M = K @ R^T
    const float f = 525.0f, cx = 320.0f, cy = 240.0f;
    float M00 = f*R[0] + cx*R[2];
    float M01 = f*R[3] + cx*R[5];
    float M02 = f*R[6] + cx*R[8];
    float M10 = f*R[1] + cy*R[2];
    float M11 = f*R[4] + cy*R[5];
    float M12 = f*R[7] + cy*R[8];
    float M20 = R[2], M21 = R[5], M22 = R[8];
    float Cx = C[0], Cy = C[1], Cz = C[2];

    double accP = 0.0, accB = 0.0;

    for (int tile = blockIdx.x; tile < ntiles; tile += gridDim.x) {
        int base = tile * TILE;
        int cnt  = min(TILE, n - base);

        __syncthreads();   // previous tile's compute done before overwrite

        if (cnt == TILE) {
            // fully coalesced float4 loads
            const float4* gp = (const float4*)(pose + (size_t)base * 63);
            float4* sp = (float4*)smPose;
            #pragma unroll 4
            for (int i = tid; i < TILE * 63 / 4; i += THREADS) sp[i] = gp[i];
            const float4* ge = (const float4*)(est + (size_t)base * 42);
            float4* se = (float4*)smEst;
            #pragma unroll 4
            for (int i = tid; i < TILE * 42 / 4; i += THREADS) se[i] = ge[i];
        } else {
            for (int i = tid; i < cnt * 63; i += THREADS)
                smPose[i] = pose[(size_t)base * 63 + i];
            for (int i = tid; i < cnt * 42; i += THREADS)
                smEst[i] = est[(size_t)base * 42 + i];
        }

        __syncthreads();

        if (tid < cnt) {
            const float* P = smPose + tid * 63;
            const float* E = smEst  + tid * 42;

            float psum = 0.0f;
            #pragma unroll
            for (int j = 0; j < NJ; j++) {
                float dx = P[j]        - Cx;
                float dy = P[NJ + j]   - Cy;
                float dz = P[2*NJ + j] - Cz;
                float px = M00*dx + M01*dy + M02*dz;
                float py = M10*dx + M11*dy + M12*dz;
                float pz = M20*dx + M21*dy + M22*dz;
                float inv = 1.0f / pz;
                float u = px * inv - E[j];
                float v = py * inv - E[NJ + j];
                psum += u*u + v*v;
            }

            float bsum = 0.0f;
            #pragma unroll
            for (int j = 0; j < NB; j++) {
                int a = smConn[2*j];
                int b = smConn[2*j + 1];
                float dx = P[a]        - P[b];
                float dy = P[NJ + a]   - P[NJ + b];
                float dz = P[2*NJ + a] - P[2*NJ + b];
                float sq = dx*dx + dy*dy + dz*dz;
                float t  = smBl[j] - sq;
                bsum += t*t;
            }

            accP += (double)psum;
            accB += (double)bsum;
        }
    }

    // block reduce
    #pragma unroll
    for (int o = 16; o > 0; o >>= 1) {
        accP += __shfl_down_sync(0xffffffffu, accP, o);
        accB += __shfl_down_sync(0xffffffffu, accB, o);
    }
    __shared__ double sP[4], sB[4];
    int lane = tid & 31, wid = tid >> 5;
    if (lane == 0) { sP[wid] = accP; sB[wid] = accB; }
    __syncthreads();
    if (wid == 0) {
        accP = (lane < 4) ? sP[lane] : 0.0;
        accB = (lane < 4) ? sB[lane] : 0.0;
        #pragma unroll
        for (int o = 2; o > 0; o >>= 1) {
            accP += __shfl_down_sync(0xffffffffu, accP, o);
            accB += __shfl_down_sync(0xffffffffu, accB, o);
        }
        if (lane == 0) { g_partP[blockIdx.x] = accP; g_partB[blockIdx.x] = accB; }
    }
}

__global__ __launch_bounds__(256) void k_final(float* __restrict__ out,
                                               int n, int nblocks) {
    double accP = 0.0, accB = 0.0;
    for (int i = threadIdx.x; i < nblocks; i += 256) {
        accP += g_partP[i];
        accB += g_partB[i];
    }
    #pragma unroll
    for (int o = 16; o > 0; o >>= 1) {
        accP += __shfl_down_sync(0xffffffffu, accP, o);
        accB += __shfl_down_sync(0xffffffffu, accB, o);
    }
    __shared__ double sP[8], sB[8];
    int lane = threadIdx.x & 31, wid = threadIdx.x >> 5;
    if (lane == 0) { sP[wid] = accP; sB[wid] = accB; }
    __syncthreads();
    if (wid == 0) {
        accP = (lane < 8) ? sP[lane] : 0.0;
        accB = (lane < 8) ? sB[lane] : 0.0;
        #pragma unroll
        for (int o = 4; o > 0; o >>= 1) {
            accP += __shfl_down_sync(0xffffffffu, accP, o);
            accB += __shfl_down_sync(0xffffffffu, accB, o);
        }
        if (lane == 0) {
            double invB = 1.0 / (double)n;
            double proj = accP * invB / (2.0 * NJ);
            double bone = accB * invB / (double)NB;
            out[0] = (float)(0.33 * proj + 0.5 * bone);
        }
    }
}

extern "C" void kernel_launch(void* const* d_in, const int* in_sizes, int n_in,
                              void* d_out, int out_size) {
    const float*     pose = (const float*)d_in[0];      // [B,3,21]
    const float*     est  = (const float*)d_in[1];      // [B,2,21]
    const float*     bl   = (const float*)d_in[2];      // [20]
    const float*     R    = (const float*)d_in[3];      // [3,3]
    const float*     C    = (const float*)d_in[4];      // [3,1]
    const long long* conn = (const long long*)d_in[5];  // [20,2]
    float* out = (float*)d_out;

    int n = in_sizes[0] / (3 * NJ);
    int ntiles = (n + TILE - 1) / TILE;
    int blocks = ntiles < 444 ? ntiles : 444;   // 3 blocks/SM on 148 SMs
    if (blocks > MAXBLK) blocks = MAXBLK;

    cudaFuncSetAttribute(k_loss, cudaFuncAttributeMaxDynamicSharedMemorySize,
                         SMEM_BYTES);
    k_loss<<<blocks, THREADS, SMEM_BYTES>>>(pose, est, bl, R, C, conn, n, ntiles);
    k_final<<<1, 256>>>(out, n, blocks);
}

// round 3
// speedup vs baseline: 3.2499x; 1.2580x over previous
#include <cuda_runtime.h>

// pose3d_future loss, double-buffered cp.async pipeline.
// P: [B,3,21] f32, E: [B,2,21] f32, bl: [20], R: [3,3], C: [3,1], conn: [20,2] i64

#define NJ 21
#define NB 20
#define TILE 128
#define THREADS 128
#define MAXBLK 1024

#define POSE_F 63                 // floats per sample (pose)
#define EST_F  42                 // floats per sample (est)
#define POSE_B (POSE_F * 4)       // 252 bytes
#define EST_B  (EST_F * 4)        // 168 bytes
#define TILE_POSE_F (TILE * POSE_F)
#define TILE_EST_F  (TILE * EST_F)
#define BUF_F (TILE_POSE_F + TILE_EST_F)      // 13440 floats per buffer
#define SM_BL   (2 * BUF_F)
#define SM_CONN (SM_BL + NB)
#define SM_FLOATS (SM_CONN + 2 * NB)
#define SMEM_BYTES (SM_FLOATS * 4)

__device__ double g_partP[MAXBLK];
__device__ double g_partB[MAXBLK];
__device__ unsigned int g_ticket;   // zero-initialized; reset by last block

__device__ __forceinline__ void cp16(unsigned int dst, const void* src, int nbytes) {
    asm volatile("cp.async.cg.shared.global [%0], [%1], 16, %2;\n"
                 :: "r"(dst), "l"(src), "r"(nbytes));
}
__device__ __forceinline__ void cp_commit() {
    asm volatile("cp.async.commit_group;\n");
}
__device__ __forceinline__ void cp_wait1() {
    asm volatile("cp.async.wait_group 1;\n");
}
__device__ __forceinline__ void cp_wait0() {
    asm volatile("cp.async.wait_group 0;\n");
}

__global__ __launch_bounds__(THREADS) void k_loss(
    const float* __restrict__ pose,     // [B,3,21]
    const float* __restrict__ est,      // [B,2,21]
    const float* __restrict__ bl,       // [20]
    const float* __restrict__ R,        // [3,3]
    const float* __restrict__ C,        // [3,1]
    const long long* __restrict__ conn, // [20,2]
    float* __restrict__ out,
    int n, int ntiles, int nblocks)
{
    extern __shared__ float sm[];
    float* smBl   = sm + SM_BL;
    int*   smConn = (int*)(sm + SM_CONN);

    int tid = threadIdx.x;

    if (tid < NB) {
        smBl[tid] = bl[tid];
        smConn[2 * tid]     = (int)conn[2 * tid];
        smConn[2 * tid + 1] = (int)conn[2 * tid + 1];
    }

    // M = K @ R^T
    const float f = 525.0f, cx = 320.0f, cy = 240.0f;
    float M00 = f*R[0] + cx*R[2];
    float M01 = f*R[3] + cx*R[5];
    float M02 = f*R[6] + cx*R[8];
    float M10 = f*R[1] + cy*R[2];
    float M11 = f*R[4] + cy*R[5];
    float M12 = f*R[7] + cy*R[8];
    float M20 = R[2], M21 = R[5], M22 = R[8];
    float Cx = C[0], Cy = C[1], Cz = C[2];

    unsigned int smemBase = (unsigned int)__cvta_generic_to_shared(sm);

    // ---- prefetch helper (inlined twice via lambda-like macro) ----
    #define PREFETCH(tileIdx, bufIdx)                                           \
    do {                                                                        \
        int _base = (tileIdx) * TILE;                                           \
        int _cnt  = min(TILE, n - _base);                                       \
        const char* _ps = (const char*)pose + (size_t)_base * POSE_B;           \
        const char* _es = (const char*)est  + (size_t)_base * EST_B;            \
        unsigned int _sp = smemBase + (bufIdx) * (BUF_F * 4);                   \
        unsigned int _se = _sp + TILE_POSE_F * 4;                               \
        int _pb = _cnt * POSE_B;                                                \
        int _eb = _cnt * EST_B;                                                 \
        for (int c = tid * 16; c < _pb; c += THREADS * 16)                      \
            cp16(_sp + c, _ps + c, min(16, _pb - c));                           \
        for (int c = tid * 16; c < _eb; c += THREADS * 16)                      \
            cp16(_se + c, _es + c, min(16, _eb - c));                           \
    } while (0)

    double accP = 0.0, accB = 0.0;

    int t0 = blockIdx.x;
    if (t0 < ntiles) {
        PREFETCH(t0, 0);
    }
    cp_commit();

    int k = 0;
    for (int t = t0; t < ntiles; t += gridDim.x, k++) {
        int tn = t + gridDim.x;
        if (tn < ntiles) {
            PREFETCH(tn, (k + 1) & 1);
        }
        cp_commit();
        cp_wait1();              // tile t's group is complete
        __syncthreads();         // all threads' copies visible

        int base = t * TILE;
        int cnt  = min(TILE, n - base);
        const float* buf = sm + (k & 1) * BUF_F;

        if (tid < cnt) {
            const float* P = buf + tid * POSE_F;
            const float* E = buf + TILE_POSE_F + tid * EST_F;

            float psum = 0.0f;
            #pragma unroll
            for (int j = 0; j < NJ; j++) {
                float dx = P[j]        - Cx;
                float dy = P[NJ + j]   - Cy;
                float dz = P[2*NJ + j] - Cz;
                float px = M00*dx + M01*dy + M02*dz;
                float py = M10*dx + M11*dy + M12*dz;
                float pz = M20*dx + M21*dy + M22*dz;
                float inv = __fdividef(1.0f, pz);
                float u = px * inv - E[j];
                float v = py * inv - E[NJ + j];
                psum += u*u + v*v;
            }

            float bsum = 0.0f;
            #pragma unroll
            for (int j = 0; j < NB; j++) {
                int a = smConn[2*j];
                int b = smConn[2*j + 1];
                float dx = P[a]        - P[b];
                float dy = P[NJ + a]   - P[NJ + b];
                float dz = P[2*NJ + a] - P[2*NJ + b];
                float sq = dx*dx + dy*dy + dz*dz;
                float tt = smBl[j] - sq;
                bsum += tt*tt;
            }

            accP += (double)psum;
            accB += (double)bsum;
        }

        __syncthreads();   // compute done before buffer (k&1) is re-prefetched
    }
    cp_wait0();

    // block reduce
    #pragma unroll
    for (int o = 16; o > 0; o >>= 1) {
        accP += __shfl_down_sync(0xffffffffu, accP, o);
        accB += __shfl_down_sync(0xffffffffu, accB, o);
    }
    __shared__ double sP[4], sB[4];
    __shared__ bool isLast;
    int lane = tid & 31, wid = tid >> 5;
    if (lane == 0) { sP[wid] = accP; sB[wid] = accB; }
    __syncthreads();
    if (tid == 0) {
        double aP = sP[0] + sP[1] + sP[2] + sP[3];
        double aB = sB[0] + sB[1] + sB[2] + sB[3];
        g_partP[blockIdx.x] = aP;
        g_partB[blockIdx.x] = aB;
        __threadfence();
        unsigned int t = atomicAdd(&g_ticket, 1u);
        isLast = (t == (unsigned int)(nblocks - 1));
    }
    __syncthreads();

    if (isLast) {
        double aP = 0.0, aB = 0.0;
        for (int i = tid; i < nblocks; i += THREADS) {
            aP += g_partP[i];
            aB += g_partB[i];
        }
        #pragma unroll
        for (int o = 16; o > 0; o >>= 1) {
            aP += __shfl_down_sync(0xffffffffu, aP, o);
            aB += __shfl_down_sync(0xffffffffu, aB, o);
        }
        if (lane == 0) { sP[wid] = aP; sB[wid] = aB; }
        __syncthreads();
        if (tid == 0) {
            aP = sP[0] + sP[1] + sP[2] + sP[3];
            aB = sB[0] + sB[1] + sB[2] + sB[3];
            double invB = 1.0 / (double)n;
            double proj = aP * invB / (2.0 * NJ);
            double bone = aB * invB / (double)NB;
            out[0] = (float)(0.33 * proj + 0.5 * bone);
            g_ticket = 0;   // reset for next graph replay (deterministic)
        }
    }
}

extern "C" void kernel_launch(void* const* d_in, const int* in_sizes, int n_in,
                              void* d_out, int out_size) {
    const float*     pose = (const float*)d_in[0];
    const float*     est  = (const float*)d_in[1];
    const float*     bl   = (const float*)d_in[2];
    const float*     R    = (const float*)d_in[3];
    const float*     C    = (const float*)d_in[4];
    const long long* conn = (const long long*)d_in[5];
    float* out = (float*)d_out;

    int n = in_sizes[0] / (3 * NJ);
    int ntiles = (n + TILE - 1) / TILE;
    int blocks = 2 * 148;               // 2 blocks/SM (107.8KB smem each)
    if (blocks > ntiles) blocks = ntiles;
    if (blocks > MAXBLK) blocks = MAXBLK;

    static int attr_set = 0;
    cudaFuncSetAttribute(k_loss, cudaFuncAttributeMaxDynamicSharedMemorySize,
                         SMEM_BYTES);
    (void)attr_set;

    k_loss<<<blocks, THREADS, SMEM_BYTES>>>(pose, est, bl, R, C, conn, out,
                                            n, ntiles, blocks);
}

// round 4
// speedup vs baseline: 3.9662x; 1.2204x over previous
#include <cuda_runtime.h>

// pose3d_future loss — single-buffer tiles, 4 blocks/SM for cross-block
// memory/compute overlap.
// P: [B,3,21] f32, E: [B,2,21] f32, bl: [20], R: [3,3], C: [3,1], conn: [20,2] i64

#define NJ 21
#define NB 20
#define TILE 128
#define THREADS 128
#define MAXBLK 1024

#define POSE_F 63
#define EST_F  42
#define POSE_B (POSE_F * 4)
#define EST_B  (EST_F * 4)
#define TILE_POSE_F (TILE * POSE_F)
#define TILE_EST_F  (TILE * EST_F)
#define BUF_F (TILE_POSE_F + TILE_EST_F)    // 13440 floats = 53760 B
#define SM_BL   BUF_F
#define SM_CONN (SM_BL + NB)
#define SM_FLOATS (SM_CONN + 2 * NB)
#define SMEM_BYTES (SM_FLOATS * 4)          // ~54 KB -> 4 blocks/SM

__device__ double g_partP[MAXBLK];
__device__ double g_partB[MAXBLK];
__device__ unsigned int g_ticket;

__device__ __forceinline__ void cp16(unsigned int dst, const void* src, int nbytes) {
    asm volatile("cp.async.cg.shared.global [%0], [%1], 16, %2;\n"
                 :: "r"(dst), "l"(src), "r"(nbytes));
}
__device__ __forceinline__ void cp_commit() {
    asm volatile("cp.async.commit_group;\n");
}
__device__ __forceinline__ void cp_wait0() {
    asm volatile("cp.async.wait_group 0;\n");
}

__global__ __launch_bounds__(THREADS) void k_loss(
    const float* __restrict__ pose,
    const float* __restrict__ est,
    const float* __restrict__ bl,
    const float* __restrict__ R,
    const float* __restrict__ C,
    const long long* __restrict__ conn,
    float* __restrict__ out,
    int n, int ntiles, int nblocks)
{
    extern __shared__ float sm[];
    float* smBl   = sm + SM_BL;
    int*   smConn = (int*)(sm + SM_CONN);

    int tid = threadIdx.x;

    if (tid < NB) {
        smBl[tid] = bl[tid];
        smConn[2 * tid]     = (int)conn[2 * tid];
        smConn[2 * tid + 1] = (int)conn[2 * tid + 1];
    }

    // M = K @ R^T
    const float f = 525.0f, cx = 320.0f, cy = 240.0f;
    float M00 = f*R[0] + cx*R[2];
    float M01 = f*R[3] + cx*R[5];
    float M02 = f*R[6] + cx*R[8];
    float M10 = f*R[1] + cy*R[2];
    float M11 = f*R[4] + cy*R[5];
    float M12 = f*R[7] + cy*R[8];
    float M20 = R[2], M21 = R[5], M22 = R[8];
    float Cx = C[0], Cy = C[1], Cz = C[2];

    unsigned int smemBase = (unsigned int)__cvta_generic_to_shared(sm);
    unsigned int spBase = smemBase;
    unsigned int seBase = smemBase + TILE_POSE_F * 4;

    double accP = 0.0, accB = 0.0;

    for (int t = blockIdx.x; t < ntiles; t += gridDim.x) {
        int base = t * TILE;
        int cnt  = min(TILE, n - base);

        __syncthreads();    // previous tile's compute fully done

        {   // stage tile (front-batched async copies)
            const char* ps = (const char*)pose + (size_t)base * POSE_B;
            const char* es = (const char*)est  + (size_t)base * EST_B;
            int pb = cnt * POSE_B;
            int eb = cnt * EST_B;
            #pragma unroll 4
            for (int c = tid * 16; c < pb; c += THREADS * 16)
                cp16(spBase + c, ps + c, min(16, pb - c));
            #pragma unroll 4
            for (int c = tid * 16; c < eb; c += THREADS * 16)
                cp16(seBase + c, es + c, min(16, eb - c));
        }
        cp_commit();
        cp_wait0();
        __syncthreads();

        if (tid < cnt) {
            const float* P = sm + tid * POSE_F;
            const float* E = sm + TILE_POSE_F + tid * EST_F;

            float psum = 0.0f;
            #pragma unroll
            for (int j = 0; j < NJ; j++) {
                float dx = P[j]        - Cx;
                float dy = P[NJ + j]   - Cy;
                float dz = P[2*NJ + j] - Cz;
                float px = M00*dx + M01*dy + M02*dz;
                float py = M10*dx + M11*dy + M12*dz;
                float pz = M20*dx + M21*dy + M22*dz;
                float inv = __fdividef(1.0f, pz);
                float u = px * inv - E[j];
                float v = py * inv - E[NJ + j];
                psum += u*u + v*v;
            }

            float bsum = 0.0f;
            #pragma unroll
            for (int j = 0; j < NB; j++) {
                int a = smConn[2*j];
                int b = smConn[2*j + 1];
                float dx = P[a]        - P[b];
                float dy = P[NJ + a]   - P[NJ + b];
                float dz = P[2*NJ + a] - P[2*NJ + b];
                float sq = dx*dx + dy*dy + dz*dz;
                float tt = smBl[j] - sq;
                bsum += tt*tt;
            }

            accP += (double)psum;
            accB += (double)bsum;
        }
    }

    // block reduce
    #pragma unroll
    for (int o = 16; o > 0; o >>= 1) {
        accP += __shfl_down_sync(0xffffffffu, accP, o);
        accB += __shfl_down_sync(0xffffffffu, accB, o);
    }
    __shared__ double sP[4], sB[4];
    __shared__ bool isLast;
    int lane = tid & 31, wid = tid >> 5;
    if (lane == 0) { sP[wid] = accP; sB[wid] = accB; }
    __syncthreads();
    if (tid == 0) {
        double aP = sP[0] + sP[1] + sP[2] + sP[3];
        double aB = sB[0] + sB[1] + sB[2] + sB[3];
        g_partP[blockIdx.x] = aP;
        g_partB[blockIdx.x] = aB;
        __threadfence();
        unsigned int tk = atomicAdd(&g_ticket, 1u);
        isLast = (tk == (unsigned int)(nblocks - 1));
    }
    __syncthreads();

    if (isLast) {
        double aP = 0.0, aB = 0.0;
        for (int i = tid; i < nblocks; i += THREADS) {
            aP += g_partP[i];
            aB += g_partB[i];
        }
        #pragma unroll
        for (int o = 16; o > 0; o >>= 1) {
            aP += __shfl_down_sync(0xffffffffu, aP, o);
            aB += __shfl_down_sync(0xffffffffu, aB, o);
        }
        if (lane == 0) { sP[wid] = aP; sB[wid] = aB; }
        __syncthreads();
        if (tid == 0) {
            aP = sP[0] + sP[1] + sP[2] + sP[3];
            aB = sB[0] + sB[1] + sB[2] + sB[3];
            double invB = 1.0 / (double)n;
            double proj = aP * invB / (2.0 * NJ);
            double bone = aB * invB / (double)NB;
            out[0] = (float)(0.33 * proj + 0.5 * bone);
            g_ticket = 0;   // reset for next graph replay
        }
    }
}

extern "C" void kernel_launch(void* const* d_in, const int* in_sizes, int n_in,
                              void* d_out, int out_size) {
    const float*     pose = (const float*)d_in[0];
    const float*     est  = (const float*)d_in[1];
    const float*     bl   = (const float*)d_in[2];
    const float*     R    = (const float*)d_in[3];
    const float*     C    = (const float*)d_in[4];
    const long long* conn = (const long long*)d_in[5];
    float* out = (float*)d_out;

    int n = in_sizes[0] / (3 * NJ);
    int ntiles = (n + TILE - 1) / TILE;
    int blocks = 4 * 148;                // 4 blocks/SM, single 54KB buffer each
    if (blocks > ntiles) blocks = ntiles;
    if (blocks > MAXBLK) blocks = MAXBLK;

    cudaFuncSetAttribute(k_loss, cudaFuncAttributeMaxDynamicSharedMemorySize,
                         SMEM_BYTES);
    k_loss<<<blocks, THREADS, SMEM_BYTES>>>(pose, est, bl, R, C, conn, out,
                                            n, ntiles, blocks);
}